// round 1
// baseline (speedup 1.0000x reference)
#include <cuda_runtime.h>

#define NN   50000
#define NE   800000
#define H    128
#define NRBF 32
#define NG   500

// ---------------- scratch (device globals; no runtime allocation) ----------------
__device__ float g_h[NN * H];                 // node features, updated in place per layer
__device__ float g_bdac[NN * 512];            // per node: B(128)|D(128)|A(128)|C(128)
__device__ float g_cfcs[NE * 256];            // per edge: cf(128)|cs(128)   (~819 MB)
__device__ int   g_off[NN + 1];               // CSR offsets by dst
__device__ int   g_cursor[NN];
__device__ int   g_src[NE];                   // CSR: src node per slot
__device__ int   g_eid[NE];                   // CSR: original edge id per slot
__device__ float g_pool[NG * H];
__device__ float g_cnt[NG];
__device__ float g_wn[H * 512];               // packed node weights (128 x 512)
__device__ float g_bn[512];                   // packed node bias
__device__ float g_we[NRBF * 256];            // packed edge weights (32 x 256)
__device__ float g_bzero[512];                // stays zero (zero-init, never written)

// ---------------- init ----------------
__global__ void k_zero() {
    int i = blockIdx.x * blockDim.x + threadIdx.x;
    if (i <= NN)     g_off[i] = 0;
    if (i <  NN)     g_cursor[i] = 0;
    if (i <  NG * H) g_pool[i] = 0.f;
    if (i <  NG)     g_cnt[i] = 0.f;
}

__global__ void k_embed(const int* __restrict__ x, const float* __restrict__ emb) {
    int idx = blockIdx.x * blockDim.x + threadIdx.x;
    if (idx >= NN * H) return;
    int i = idx >> 7, c = idx & (H - 1);
    g_h[idx] = emb[x[i] * H + c];
}

// ---------------- CSR build (by dst) ----------------
__global__ void k_count(const int* __restrict__ ei) {
    int e = blockIdx.x * blockDim.x + threadIdx.x;
    if (e >= NE) return;
    atomicAdd(&g_off[ei[NE + e] + 1], 1);
}

__global__ void k_scan() {   // inclusive scan of g_off[0..NN]; single block, 1024 threads
    __shared__ int s[1024];
    __shared__ int carry;
    int tid = threadIdx.x;
    if (tid == 0) carry = 0;
    __syncthreads();
    for (int base = 0; base < NN + 1; base += 1024) {
        int i = base + tid;
        int v = (i <= NN) ? g_off[i] : 0;
        s[tid] = v;
        __syncthreads();
        #pragma unroll
        for (int d = 1; d < 1024; d <<= 1) {
            int t = (tid >= d) ? s[tid - d] : 0;
            __syncthreads();
            s[tid] += t;
            __syncthreads();
        }
        if (i <= NN) g_off[i] = s[tid] + carry;
        __syncthreads();
        if (tid == 0) carry += s[1023];
        __syncthreads();
    }
}

__global__ void k_scatter(const int* __restrict__ ei) {
    int e = blockIdx.x * blockDim.x + threadIdx.x;
    if (e >= NE) return;
    int s = ei[e], d = ei[NE + e];
    int p = g_off[d] + atomicAdd(&g_cursor[d], 1);
    g_src[p] = s;
    g_eid[p] = e;
}

// ---------------- per-layer weight packing ----------------
// node cols: [0,128)=B uses Wf[128:256], [128,256)=D uses Ws[128:256],
//            [256,384)=A uses Wf[0:128] (+bf), [384,512)=C uses Ws[0:128] (+bs)
// edge cols: [0,128)=cf uses Wf[256:288], [128,256)=cs uses Ws[256:288]
__global__ void k_pack(const float* __restrict__ Wf, const float* __restrict__ bf,
                       const float* __restrict__ Ws, const float* __restrict__ bs) {
    int idx = blockIdx.x * blockDim.x + threadIdx.x;
    if (idx < H * 512) {
        int k = idx >> 9, j = idx & 511;
        float v;
        if (j < 128)      v = Wf[(128 + k) * H + j];
        else if (j < 256) v = Ws[(128 + k) * H + (j - 128)];
        else if (j < 384) v = Wf[k * H + (j - 256)];
        else              v = Ws[k * H + (j - 384)];
        g_wn[idx] = v;
    } else if (idx < H * 512 + 512) {
        int j = idx - H * 512;
        g_bn[j] = (j < 256) ? 0.f : ((j < 384) ? bf[j - 256] : bs[j - 384]);
    } else if (idx < H * 512 + 512 + NRBF * 256) {
        int t = idx - (H * 512 + 512);
        int k = t >> 8, j = t & 255;
        g_we[t] = (j < 128) ? Wf[(256 + k) * H + j] : Ws[(256 + k) * H + (j - 128)];
    }
}

// ---------------- fp32 SGEMM: C[M,N] = A[M,K] @ W[K,N] + bias[N] ----------------
// 128x128 block tile, K-step 8, 256 threads, 8x8 per thread
__global__ __launch_bounds__(256) void sgemm(const float* __restrict__ A,
                                             const float* __restrict__ W,
                                             const float* __restrict__ bias,
                                             float* __restrict__ C,
                                             int M, int N, int K) {
    __shared__ float As[8][136];
    __shared__ float Bs[8][128];
    int tid = threadIdx.x;
    int tx = tid & 15, ty = tid >> 4;
    int row0 = blockIdx.y * 128;
    int col0 = blockIdx.x * 128;
    int ar = tid >> 1, ac = (tid & 1) * 4;
    int wr = tid >> 5, wc = (tid & 31) * 4;

    float acc[8][8];
    #pragma unroll
    for (int i = 0; i < 8; i++)
        #pragma unroll
        for (int j = 0; j < 8; j++) acc[i][j] = 0.f;

    for (int kt = 0; kt < K; kt += 8) {
        float4 av = make_float4(0.f, 0.f, 0.f, 0.f);
        int gr = row0 + ar;
        if (gr < M) av = *(const float4*)(A + (size_t)gr * K + kt + ac);
        As[ac + 0][ar] = av.x; As[ac + 1][ar] = av.y;
        As[ac + 2][ar] = av.z; As[ac + 3][ar] = av.w;
        *(float4*)&Bs[wr][wc] = *(const float4*)(W + (size_t)(kt + wr) * N + col0 + wc);
        __syncthreads();
        #pragma unroll
        for (int k = 0; k < 8; k++) {
            float a[8], b[8];
            float4 t;
            t = *(const float4*)&As[k][ty * 8];     a[0]=t.x; a[1]=t.y; a[2]=t.z; a[3]=t.w;
            t = *(const float4*)&As[k][ty * 8 + 4]; a[4]=t.x; a[5]=t.y; a[6]=t.z; a[7]=t.w;
            t = *(const float4*)&Bs[k][tx * 8];     b[0]=t.x; b[1]=t.y; b[2]=t.z; b[3]=t.w;
            t = *(const float4*)&Bs[k][tx * 8 + 4]; b[4]=t.x; b[5]=t.y; b[6]=t.z; b[7]=t.w;
            #pragma unroll
            for (int i = 0; i < 8; i++)
                #pragma unroll
                for (int j = 0; j < 8; j++)
                    acc[i][j] = fmaf(a[i], b[j], acc[i][j]);
        }
        __syncthreads();
    }
    #pragma unroll
    for (int i = 0; i < 8; i++) {
        int r = row0 + ty * 8 + i;
        if (r >= M) continue;
        #pragma unroll
        for (int j = 0; j < 8; j += 4) {
            int c = col0 + tx * 8 + j;
            float4 o;
            o.x = acc[i][j + 0] + bias[c + 0];
            o.y = acc[i][j + 1] + bias[c + 1];
            o.z = acc[i][j + 2] + bias[c + 2];
            o.w = acc[i][j + 3] + bias[c + 3];
            *(float4*)(C + (size_t)r * N + c) = o;
        }
    }
}

// ---------------- edge aggregation: one warp per dst node ----------------
__device__ __forceinline__ float gatef(float gf, float gs) {
    float sig = __fdividef(1.f, 1.f + __expf(-gf));
    float t   = __expf(-fabsf(gs));
    float sp  = fmaxf(gs, 0.f) + __logf(1.f + t);
    return sig * sp;
}

__global__ __launch_bounds__(256) void k_edge() {
    int w = (blockIdx.x * blockDim.x + threadIdx.x) >> 5;
    int lane = threadIdx.x & 31;
    if (w >= NN) return;
    int c4 = lane * 4;
    float4 acc = *(const float4*)&g_h[w * H + c4];
    const float* nd = g_bdac + (size_t)w * 512;
    float4 Av = *(const float4*)(nd + 256 + c4);   // h[dst]@Wf + bf
    float4 Cv = *(const float4*)(nd + 384 + c4);   // h[dst]@Ws + bs
    int e0 = g_off[w], e1 = g_off[w + 1];
    for (int e = e0; e < e1; e++) {
        int src = g_src[e];
        int eid = g_eid[e];
        const float* sd = g_bdac + (size_t)src * 512;
        float4 Bv = *(const float4*)(sd + c4);          // h[src]@Wf
        float4 Dv = *(const float4*)(sd + 128 + c4);    // h[src]@Ws
        const float* ed = g_cfcs + (size_t)eid * 256;
        float4 cf = *(const float4*)(ed + c4);
        float4 cs = *(const float4*)(ed + 128 + c4);
        acc.x += gatef(Av.x + Bv.x + cf.x, Cv.x + Dv.x + cs.x);
        acc.y += gatef(Av.y + Bv.y + cf.y, Cv.y + Dv.y + cs.y);
        acc.z += gatef(Av.z + Bv.z + cf.z, Cv.z + Dv.z + cs.z);
        acc.w += gatef(Av.w + Bv.w + cf.w, Cv.w + Dv.w + cs.w);
    }
    acc.x = fmaxf(acc.x, 0.f);
    acc.y = fmaxf(acc.y, 0.f);
    acc.z = fmaxf(acc.z, 0.f);
    acc.w = fmaxf(acc.w, 0.f);
    *(float4*)&g_h[w * H + c4] = acc;
}

// ---------------- pooling + final linear ----------------
__global__ void k_pool(const int* __restrict__ batch) {
    int idx = blockIdx.x * blockDim.x + threadIdx.x;
    if (idx >= NN * H) return;
    int i = idx >> 7, c = idx & (H - 1);
    atomicAdd(&g_pool[batch[i] * H + c], g_h[idx]);
}

__global__ void k_cnt(const int* __restrict__ batch) {
    int i = blockIdx.x * blockDim.x + threadIdx.x;
    if (i >= NN) return;
    atomicAdd(&g_cnt[batch[i]], 1.f);
}

__global__ void k_final(const float* __restrict__ Wlin, const float* __restrict__ blin,
                        float* __restrict__ out) {
    __shared__ float p[H];
    int g = blockIdx.x, j = threadIdx.x;
    float cnt = fmaxf(g_cnt[g], 1.f);
    p[j] = g_pool[g * H + j] / cnt;
    __syncthreads();
    float s = blin[j];
    #pragma unroll 8
    for (int k = 0; k < H; k++) s = fmaf(p[k], Wlin[k * H + j], s);
    out[g * H + j] = s;
}

// ---------------- launch ----------------
extern "C" void kernel_launch(void* const* d_in, const int* in_sizes, int n_in,
                              void* d_out, int out_size) {
    const int*   x     = (const int*)d_in[0];
    const int*   ei    = (const int*)d_in[1];
    const float* eattr = (const float*)d_in[2];
    const int*   batch = (const int*)d_in[3];
    const float* emb   = (const float*)d_in[4];
    const float* Wf[3] = {(const float*)d_in[5],  (const float*)d_in[9],  (const float*)d_in[13]};
    const float* bf[3] = {(const float*)d_in[6],  (const float*)d_in[10], (const float*)d_in[14]};
    const float* Ws[3] = {(const float*)d_in[7],  (const float*)d_in[11], (const float*)d_in[15]};
    const float* bs[3] = {(const float*)d_in[8],  (const float*)d_in[12], (const float*)d_in[16]};
    const float* Wlin  = (const float*)d_in[17];
    const float* blin  = (const float*)d_in[18];
    float* out = (float*)d_out;

    float *p_h, *p_wn, *p_bn, *p_we, *p_bz, *p_bdac, *p_cfcs;
    cudaGetSymbolAddress((void**)&p_h,    g_h);
    cudaGetSymbolAddress((void**)&p_wn,   g_wn);
    cudaGetSymbolAddress((void**)&p_bn,   g_bn);
    cudaGetSymbolAddress((void**)&p_we,   g_we);
    cudaGetSymbolAddress((void**)&p_bz,   g_bzero);
    cudaGetSymbolAddress((void**)&p_bdac, g_bdac);
    cudaGetSymbolAddress((void**)&p_cfcs, g_cfcs);

    k_zero<<<(NG * H + 255) / 256, 256>>>();
    k_embed<<<(NN * H + 255) / 256, 256>>>(x, emb);
    k_count<<<(NE + 255) / 256, 256>>>(ei);
    k_scan<<<1, 1024>>>();
    k_scatter<<<(NE + 255) / 256, 256>>>(ei);

    for (int l = 0; l < 3; l++) {
        k_pack<<<(H * 512 + 512 + NRBF * 256 + 255) / 256, 256>>>(Wf[l], bf[l], Ws[l], bs[l]);
        sgemm<<<dim3(512 / 128, (NN + 127) / 128), 256>>>(p_h,   p_wn, p_bn, p_bdac, NN, 512, H);
        sgemm<<<dim3(256 / 128, NE / 128),        256>>>(eattr, p_we, p_bz, p_cfcs, NE, 256, NRBF);
        k_edge<<<(NN * 32 + 255) / 256, 256>>>();
    }

    k_pool<<<(NN * H + 255) / 256, 256>>>(batch);
    k_cnt<<<(NN + 255) / 256, 256>>>(batch);
    k_final<<<NG, H>>>(Wlin, blin, out);
}

// round 4
// speedup vs baseline: 1.3093x; 1.3093x over previous
#include <cuda_runtime.h>
#include <cuda_fp16.h>
#include <cstdint>

#define NN   50000
#define NE   800000
#define H    128
#define NG   500
#define NBLK 49            // scan blocks: 49*1024 >= 50001

// ---------------- device scratch ----------------
__device__ float   g_h[NN * H];          // fp32 node features
__device__ __half  g_hh_hi[NN * H];      // fp16 split of h (GEMM A input)
__device__ __half  g_hh_lo[NN * H];
__device__ float   g_ac[NN * 256];       // per node: A(128)|C(128) fp32
__device__ float   g_bdf[NN * 256];      // per node interleaved: B[c],D[c] fp32 pairs
__device__ __half2 g_cc[NE * H];         // per edge: half2(cf[c],cs[c])  (~410MB)
__device__ __half  g_wnt_hi[512 * 128];  // node weights, transposed [outcol][k]
__device__ __half  g_wnt_lo[512 * 128];
__device__ __half  g_wet_hi[256 * 32];   // edge weights, transposed [outcol][k]
__device__ __half  g_wet_lo[256 * 32];
__device__ float   g_bA[128], g_bC[128]; // biases bf, bs
__device__ int     g_off[NN + 1];
__device__ int     g_cursor[NN];
__device__ int     g_src[NE];
__device__ int     g_eid[NE];
__device__ int     g_bsum[NBLK], g_bpre[NBLK];
__device__ float   g_pool[NG * H];
__device__ float   g_cnt[NG];

// ---------------- warp mma helper ----------------
__device__ __forceinline__ void mma16816(float* c, uint32_t a0, uint32_t a1,
                                         uint32_t a2, uint32_t a3,
                                         uint32_t b0, uint32_t b1) {
    asm volatile("mma.sync.aligned.m16n8k16.row.col.f32.f16.f16.f32 "
                 "{%0,%1,%2,%3}, {%4,%5,%6,%7}, {%8,%9}, {%0,%1,%2,%3};"
                 : "+f"(c[0]), "+f"(c[1]), "+f"(c[2]), "+f"(c[3])
                 : "r"(a0), "r"(a1), "r"(a2), "r"(a3), "r"(b0), "r"(b1));
}

// ---------------- init / CSR ----------------
__global__ void k_zero() {
    int i = blockIdx.x * blockDim.x + threadIdx.x;
    if (i <= NN)     g_off[i] = 0;
    if (i <  NN)     g_cursor[i] = 0;
    if (i <  NG * H) g_pool[i] = 0.f;
    if (i <  NG)     g_cnt[i] = 0.f;
}

__global__ void k_embed(const int* __restrict__ x, const float* __restrict__ emb) {
    int idx = blockIdx.x * blockDim.x + threadIdx.x;
    if (idx >= NN * H) return;
    int i = idx >> 7, c = idx & (H - 1);
    float v = emb[x[i] * H + c];
    g_h[idx] = v;
    __half hi = __float2half(v);
    g_hh_hi[idx] = hi;
    g_hh_lo[idx] = __float2half(v - __half2float(hi));
}

__global__ void k_count(const int* __restrict__ ei) {
    int e = blockIdx.x * blockDim.x + threadIdx.x;
    if (e < NE) atomicAdd(&g_off[ei[NE + e] + 1], 1);
}

__global__ void k_scan1() {
    __shared__ int s[1024];
    int i = blockIdx.x * 1024 + threadIdx.x;
    int v = (i <= NN) ? g_off[i] : 0;
    s[threadIdx.x] = v;
    __syncthreads();
    #pragma unroll
    for (int d = 1; d < 1024; d <<= 1) {
        int t = (threadIdx.x >= d) ? s[threadIdx.x - d] : 0;
        __syncthreads();
        s[threadIdx.x] += t;
        __syncthreads();
    }
    if (i <= NN) g_off[i] = s[threadIdx.x];
    if (threadIdx.x == 1023) g_bsum[blockIdx.x] = s[1023];
}

__global__ void k_scan2() {
    if (threadIdx.x == 0) {
        int run = 0;
        for (int b = 0; b < NBLK; b++) { g_bpre[b] = run; run += g_bsum[b]; }
    }
}

__global__ void k_scan3() {
    int i = blockIdx.x * 1024 + threadIdx.x;
    if (blockIdx.x > 0 && i <= NN) g_off[i] += g_bpre[blockIdx.x];
}

__global__ void k_scatter(const int* __restrict__ ei) {
    int e = blockIdx.x * blockDim.x + threadIdx.x;
    if (e >= NE) return;
    int s = ei[e], d = ei[NE + e];
    int p = g_off[d] + atomicAdd(&g_cursor[d], 1);
    g_src[p] = s;
    g_eid[p] = e;
}

// ---------------- weight pack (transposed, split fp16) ----------------
// node out cols: [0,128)=B<-Wf[128:256], [128,256)=D<-Ws[128:256],
//                [256,384)=A<-Wf[0:128], [384,512)=C<-Ws[0:128]
// edge out cols: [0,128)=cf<-Wf[256:288], [128,256)=cs<-Ws[256:288]
__global__ void k_pack(const float* __restrict__ Wf, const float* __restrict__ bf,
                       const float* __restrict__ Ws, const float* __restrict__ bs) {
    int idx = blockIdx.x * blockDim.x + threadIdx.x;
    if (idx < 512 * 128) {
        int j = idx >> 7, k = idx & 127;
        float v;
        if (j < 128)      v = Wf[(128 + k) * H + j];
        else if (j < 256) v = Ws[(128 + k) * H + (j - 128)];
        else if (j < 384) v = Wf[k * H + (j - 256)];
        else              v = Ws[k * H + (j - 384)];
        __half hi = __float2half(v);
        g_wnt_hi[idx] = hi;
        g_wnt_lo[idx] = __float2half(v - __half2float(hi));
    } else if (idx < 512 * 128 + 256 * 32) {
        int t = idx - 512 * 128;
        int j = t >> 5, k = t & 31;
        float v = (j < 128) ? Wf[(256 + k) * H + j] : Ws[(256 + k) * H + (j - 128)];
        __half hi = __float2half(v);
        g_wet_hi[t] = hi;
        g_wet_lo[t] = __float2half(v - __half2float(hi));
    } else if (idx < 512 * 128 + 256 * 32 + 256) {
        int c = idx - (512 * 128 + 256 * 32);
        if (c < 128) g_bA[c] = bf[c];
        else         g_bC[c - 128] = bs[c - 128];
    }
}

// ---------------- node GEMM (split-fp16 3-pass HMMA) -----------------------------
// [128-tile,128] @ wnt^T -> BD fp32 interleave + AC fp32
// block: 256 thr = 8 warps = 8 m-groups of 16 rows. Each warp loops 8 n-chunks of 64.
__global__ __launch_bounds__(256) void gemm_node() {
    extern __shared__ __half sm[];
    __half* sH = sm;                 // 128 x 136
    __half* sL = sm + 128 * 136;     // 128 x 136
    int tid = threadIdx.x;
    int m0 = blockIdx.x * 128;

    for (int i = tid; i < 4096; i += 256) {        // 2 arrays x 128 rows x 16 uint4
        int half_sel = i >> 11;
        int r = (i >> 4) & 127, c = i & 15;
        uint4 v = make_uint4(0, 0, 0, 0);
        if (m0 + r < NN) {
            const __half* src = half_sel ? g_hh_lo : g_hh_hi;
            v = *(const uint4*)(src + (size_t)(m0 + r) * 128 + c * 8);
        }
        __half* dstp = half_sel ? sL : sH;
        *(uint4*)(dstp + r * 136 + c * 8) = v;
    }
    __syncthreads();

    int w = tid >> 5, lane = tid & 31;
    int g = lane >> 2, tig = lane & 3;
    int row_l = w * 16 + g;
    int grow0 = m0 + row_l, grow1 = grow0 + 8;

    for (int q = 0; q < 8; q++) {
        float acc[8][4];
        #pragma unroll
        for (int i = 0; i < 8; i++)
            #pragma unroll
            for (int j = 0; j < 4; j++) acc[i][j] = 0.f;

        #pragma unroll
        for (int ks = 0; ks < 8; ks++) {
            const __half* apH = sH + row_l * 136 + ks * 16 + tig * 2;
            const __half* apL = sL + row_l * 136 + ks * 16 + tig * 2;
            uint32_t aH0 = *(const uint32_t*)apH;
            uint32_t aH1 = *(const uint32_t*)(apH + 8 * 136);
            uint32_t aH2 = *(const uint32_t*)(apH + 8);
            uint32_t aH3 = *(const uint32_t*)(apH + 8 * 136 + 8);
            uint32_t aL0 = *(const uint32_t*)apL;
            uint32_t aL1 = *(const uint32_t*)(apL + 8 * 136);
            uint32_t aL2 = *(const uint32_t*)(apL + 8);
            uint32_t aL3 = *(const uint32_t*)(apL + 8 * 136 + 8);
            #pragma unroll
            for (int i = 0; i < 8; i++) {
                int t = (q < 4) ? ((i < 4) ? (q * 4 + i) : (16 + q * 4 + i - 4))
                                : (32 + (q - 4) * 8 + i);
                int n = t * 8 + g;
                int boff = n * 128 + ks * 16 + tig * 2;
                uint32_t bH0 = *(const uint32_t*)(g_wnt_hi + boff);
                uint32_t bH1 = *(const uint32_t*)(g_wnt_hi + boff + 8);
                uint32_t bL0 = *(const uint32_t*)(g_wnt_lo + boff);
                uint32_t bL1 = *(const uint32_t*)(g_wnt_lo + boff + 8);
                mma16816(acc[i], aH0, aH1, aH2, aH3, bH0, bH1);
                mma16816(acc[i], aH0, aH1, aH2, aH3, bL0, bL1);
                mma16816(acc[i], aL0, aL1, aL2, aL3, bH0, bH1);
            }
        }

        if (q < 4) {       // B|D fp32 interleaved: tile i (B) pairs with tile i+4 (D)
            #pragma unroll
            for (int i = 0; i < 4; i++) {
                int col = q * 32 + i * 8 + tig * 2;
                if (grow0 < NN) {
                    float4 o = make_float4(acc[i][0], acc[i + 4][0], acc[i][1], acc[i + 4][1]);
                    *(float4*)(g_bdf + (size_t)grow0 * 256 + col * 2) = o;
                }
                if (grow1 < NN) {
                    float4 o = make_float4(acc[i][2], acc[i + 4][2], acc[i][3], acc[i + 4][3]);
                    *(float4*)(g_bdf + (size_t)grow1 * 256 + col * 2) = o;
                }
            }
        } else {           // A|C plain fp32
            #pragma unroll
            for (int i = 0; i < 8; i++) {
                int col = (q - 4) * 64 + i * 8 + tig * 2;
                if (grow0 < NN)
                    *(float2*)(g_ac + (size_t)grow0 * 256 + col) = make_float2(acc[i][0], acc[i][1]);
                if (grow1 < NN)
                    *(float2*)(g_ac + (size_t)grow1 * 256 + col) = make_float2(acc[i][2], acc[i][3]);
            }
        }
    }
}

// ---------------- edge GEMM (split-fp16 3-pass HMMA) -----------------------------
// [64-tile,32] @ wet^T -> cc half2. block: 8 warps = 4 m-groups x 2 n-halves.
// Per warp: 8 cf tiles (nh*8+p) each paired with cs tile (+16). Full 256-col coverage.
__global__ __launch_bounds__(256) void gemm_edge(const float* __restrict__ eattr) {
    __shared__ __half sH[64 * 40];       // 80B rows (pad 8 halves)
    __shared__ __half sL[64 * 40];
    int tid = threadIdx.x;
    int m0 = blockIdx.x * 64;

    for (int i = tid; i < 512; i += 256) {         // 64 rows x 8 float4
        int r = i >> 3, c4 = (i & 7) * 4;
        float4 f = *(const float4*)(eattr + (size_t)(m0 + r) * 32 + c4);
        __half h0 = __float2half(f.x), h1 = __float2half(f.y);
        __half h2 = __float2half(f.z), h3 = __float2half(f.w);
        __half hv[4] = {h0, h1, h2, h3};
        __half lv[4] = {__float2half(f.x - __half2float(h0)),
                        __float2half(f.y - __half2float(h1)),
                        __float2half(f.z - __half2float(h2)),
                        __float2half(f.w - __half2float(h3))};
        *(uint2*)(sH + r * 40 + c4) = *(uint2*)hv;
        *(uint2*)(sL + r * 40 + c4) = *(uint2*)lv;
    }
    __syncthreads();

    int w = tid >> 5, lane = tid & 31;
    int mg = w >> 1, nh = w & 1;
    int g = lane >> 2, tig = lane & 3;
    int row_l = mg * 16 + g;

    float af[8][4], as_[8][4];
    #pragma unroll
    for (int i = 0; i < 8; i++)
        #pragma unroll
        for (int j = 0; j < 4; j++) { af[i][j] = 0.f; as_[i][j] = 0.f; }

    #pragma unroll
    for (int ks = 0; ks < 2; ks++) {
        const __half* apH = sH + row_l * 40 + ks * 16 + tig * 2;
        const __half* apL = sL + row_l * 40 + ks * 16 + tig * 2;
        uint32_t aH0 = *(const uint32_t*)apH;
        uint32_t aH1 = *(const uint32_t*)(apH + 8 * 40);
        uint32_t aH2 = *(const uint32_t*)(apH + 8);
        uint32_t aH3 = *(const uint32_t*)(apH + 8 * 40 + 8);
        uint32_t aL0 = *(const uint32_t*)apL;
        uint32_t aL1 = *(const uint32_t*)(apL + 8 * 40);
        uint32_t aL2 = *(const uint32_t*)(apL + 8);
        uint32_t aL3 = *(const uint32_t*)(apL + 8 * 40 + 8);
        #pragma unroll
        for (int p = 0; p < 8; p++) {
            int tf = nh * 8 + p;
            int nf = tf * 8 + g;
            int ns = (tf + 16) * 8 + g;
            int bof = nf * 32 + ks * 16 + tig * 2;
            int bos = ns * 32 + ks * 16 + tig * 2;
            uint32_t fH0 = *(const uint32_t*)(g_wet_hi + bof);
            uint32_t fH1 = *(const uint32_t*)(g_wet_hi + bof + 8);
            uint32_t fL0 = *(const uint32_t*)(g_wet_lo + bof);
            uint32_t fL1 = *(const uint32_t*)(g_wet_lo + bof + 8);
            uint32_t sH0 = *(const uint32_t*)(g_wet_hi + bos);
            uint32_t sH1 = *(const uint32_t*)(g_wet_hi + bos + 8);
            uint32_t sL0 = *(const uint32_t*)(g_wet_lo + bos);
            uint32_t sL1 = *(const uint32_t*)(g_wet_lo + bos + 8);
            mma16816(af[p],  aH0, aH1, aH2, aH3, fH0, fH1);
            mma16816(af[p],  aH0, aH1, aH2, aH3, fL0, fL1);
            mma16816(af[p],  aL0, aL1, aL2, aL3, fH0, fH1);
            mma16816(as_[p], aH0, aH1, aH2, aH3, sH0, sH1);
            mma16816(as_[p], aH0, aH1, aH2, aH3, sL0, sL1);
            mma16816(as_[p], aL0, aL1, aL2, aL3, sH0, sH1);
        }
    }

    int e0 = m0 + row_l;
    #pragma unroll
    for (int p = 0; p < 8; p++) {
        int col = nh * 64 + p * 8 + tig * 2;     // cf column index 0..127
        __half2 o[2];
        o[0] = __floats2half2_rn(af[p][0], as_[p][0]);
        o[1] = __floats2half2_rn(af[p][1], as_[p][1]);
        *(uint2*)(g_cc + (size_t)e0 * 128 + col) = *(uint2*)o;
        o[0] = __floats2half2_rn(af[p][2], as_[p][2]);
        o[1] = __floats2half2_rn(af[p][3], as_[p][3]);
        *(uint2*)(g_cc + (size_t)(e0 + 8) * 128 + col) = *(uint2*)o;
    }
}

// ---------------- edge aggregation: one warp per dst node ----------------
__device__ __forceinline__ float gatef(float gf, float gs) {
    float sig = __fdividef(1.f, 1.f + __expf(-gf));
    float sp  = fmaxf(gs, 0.f) + __logf(1.f + __expf(-fabsf(gs)));
    return sig * sp;
}

__global__ __launch_bounds__(256) void k_edge() {
    int w = (blockIdx.x * blockDim.x + threadIdx.x) >> 5;
    int lane = threadIdx.x & 31;
    if (w >= NN) return;
    int c4 = lane * 4;
    float4 acc = *(const float4*)&g_h[w * H + c4];
    float4 Av = *(const float4*)&g_ac[w * 256 + c4];
    float4 Cv = *(const float4*)&g_ac[w * 256 + 128 + c4];
    float4 bAv = *(const float4*)&g_bA[c4];
    float4 bCv = *(const float4*)&g_bC[c4];
    Av.x += bAv.x; Av.y += bAv.y; Av.z += bAv.z; Av.w += bAv.w;
    Cv.x += bCv.x; Cv.y += bCv.y; Cv.z += bCv.z; Cv.w += bCv.w;
    int e0 = g_off[w], e1 = g_off[w + 1];
    for (int e = e0; e < e1; e++) {
        int src = g_src[e];
        int eid = g_eid[e];
        float4 bd0 = *(const float4*)(g_bdf + (size_t)src * 256 + c4 * 2);      // B0,D0,B1,D1
        float4 bd1 = *(const float4*)(g_bdf + (size_t)src * 256 + c4 * 2 + 4);  // B2,D2,B3,D3
        uint4 ccv = *(const uint4*)(g_cc + (size_t)eid * 128 + c4);
        const __half2* ch = (const __half2*)&ccv;
        float2 c0 = __half22float2(ch[0]), c1 = __half22float2(ch[1]);
        float2 c2 = __half22float2(ch[2]), c3 = __half22float2(ch[3]);
        acc.x += gatef(Av.x + bd0.x + c0.x, Cv.x + bd0.y + c0.y);
        acc.y += gatef(Av.y + bd0.z + c1.x, Cv.y + bd0.w + c1.y);
        acc.z += gatef(Av.z + bd1.x + c2.x, Cv.z + bd1.y + c2.y);
        acc.w += gatef(Av.w + bd1.z + c3.x, Cv.w + bd1.w + c3.y);
    }
    acc.x = fmaxf(acc.x, 0.f);
    acc.y = fmaxf(acc.y, 0.f);
    acc.z = fmaxf(acc.z, 0.f);
    acc.w = fmaxf(acc.w, 0.f);
    *(float4*)&g_h[w * H + c4] = acc;
    __half hi[4], lo[4];
    hi[0] = __float2half(acc.x); lo[0] = __float2half(acc.x - __half2float(hi[0]));
    hi[1] = __float2half(acc.y); lo[1] = __float2half(acc.y - __half2float(hi[1]));
    hi[2] = __float2half(acc.z); lo[2] = __float2half(acc.z - __half2float(hi[2]));
    hi[3] = __float2half(acc.w); lo[3] = __float2half(acc.w - __half2float(hi[3]));
    *(uint2*)(g_hh_hi + w * H + c4) = *(uint2*)hi;
    *(uint2*)(g_hh_lo + w * H + c4) = *(uint2*)lo;
}

// ---------------- pooling + final linear ----------------
__global__ void k_pool(const int* __restrict__ batch) {
    int idx = blockIdx.x * blockDim.x + threadIdx.x;
    if (idx >= NN * H) return;
    int i = idx >> 7, c = idx & (H - 1);
    atomicAdd(&g_pool[batch[i] * H + c], g_h[idx]);
}

__global__ void k_cnt(const int* __restrict__ batch) {
    int i = blockIdx.x * blockDim.x + threadIdx.x;
    if (i < NN) atomicAdd(&g_cnt[batch[i]], 1.f);
}

__global__ void k_final(const float* __restrict__ Wlin, const float* __restrict__ blin,
                        float* __restrict__ out) {
    __shared__ float p[H];
    int g = blockIdx.x, j = threadIdx.x;
    float cnt = fmaxf(g_cnt[g], 1.f);
    p[j] = g_pool[g * H + j] / cnt;
    __syncthreads();
    float s = blin[j];
    #pragma unroll 8
    for (int k = 0; k < H; k++) s = fmaf(p[k], Wlin[k * H + j], s);
    out[g * H + j] = s;
}

// ---------------- launch ----------------
extern "C" void kernel_launch(void* const* d_in, const int* in_sizes, int n_in,
                              void* d_out, int out_size) {
    const int*   x     = (const int*)d_in[0];
    const int*   ei    = (const int*)d_in[1];
    const float* eattr = (const float*)d_in[2];
    const int*   batch = (const int*)d_in[3];
    const float* emb   = (const float*)d_in[4];
    const float* Wf[3] = {(const float*)d_in[5],  (const float*)d_in[9],  (const float*)d_in[13]};
    const float* bf[3] = {(const float*)d_in[6],  (const float*)d_in[10], (const float*)d_in[14]};
    const float* Ws[3] = {(const float*)d_in[7],  (const float*)d_in[11], (const float*)d_in[15]};
    const float* bs[3] = {(const float*)d_in[8],  (const float*)d_in[12], (const float*)d_in[16]};
    const float* Wlin  = (const float*)d_in[17];
    const float* blin  = (const float*)d_in[18];
    float* out = (float*)d_out;

    static int smem_set = 0;
    if (!smem_set) {
        cudaFuncSetAttribute(gemm_node, cudaFuncAttributeMaxDynamicSharedMemorySize,
                             2 * 128 * 136 * (int)sizeof(__half));
        smem_set = 1;
    }

    k_zero<<<(NG * H + 255) / 256, 256>>>();
    k_embed<<<(NN * H + 255) / 256, 256>>>(x, emb);
    k_count<<<(NE + 255) / 256, 256>>>(ei);
    k_scan1<<<NBLK, 1024>>>();
    k_scan2<<<1, 32>>>();
    k_scan3<<<NBLK, 1024>>>();
    k_scatter<<<(NE + 255) / 256, 256>>>(ei);

    for (int l = 0; l < 3; l++) {
        k_pack<<<(512 * 128 + 256 * 32 + 256 + 255) / 256, 256>>>(Wf[l], bf[l], Ws[l], bs[l]);
        gemm_node<<<(NN + 127) / 128, 256, 2 * 128 * 136 * sizeof(__half)>>>();
        gemm_edge<<<NE / 64, 256>>>(eattr);
        k_edge<<<(NN * 32 + 255) / 256, 256>>>();
    }

    k_pool<<<(NN * H + 255) / 256, 256>>>(batch);
    k_cnt<<<(NN + 255) / 256, 256>>>(batch);
    k_final<<<NG, H>>>(Wlin, blin, out);
}

// round 8
// speedup vs baseline: 1.8098x; 1.3822x over previous
#include <cuda_runtime.h>
#include <cuda_fp16.h>
#include <cstdint>

#define NN   50000
#define NE   800000
#define H    128
#define NG   500
#define NBLK 49            // scan blocks: 49*1024 >= 50001

// ---------------- device scratch ----------------
__device__ float   g_h[NN * H];          // fp32 node features
__device__ __half  g_hh_hi[NN * H];      // fp16 split of h (GEMM A input)
__device__ __half  g_hh_lo[NN * H];
__device__ float   g_ac[NN * 256];       // per node: A(128)|C(128) fp32
__device__ float   g_bdf[NN * 256];      // per node interleaved: B[c],D[c] fp32 pairs
__device__ __half2 g_cc[NE * H];         // per edge: half2(cf[c],cs[c])  (~410MB)
__device__ __half  g_ea[NE * 64];        // per edge row: 32 hi halves | 32 lo halves
__device__ uint4   g_wnp[64 * 8 * 32];   // node weight frags: [(t*8+ks)*32+lane] = b0hi,b1hi,b0lo,b1lo
__device__ uint4   g_wep[32 * 2 * 32];   // edge weight frags
__device__ float   g_bA[128], g_bC[128]; // biases bf, bs
__device__ int     g_off[NN + 1];
__device__ int     g_cursor[NN];
__device__ int     g_src[NE];
__device__ int     g_eid[NE];
__device__ int     g_bsum[NBLK], g_bpre[NBLK];
__device__ float   g_pool[NG * H];
__device__ float   g_cnt[NG];

// ---------------- helpers ----------------
__device__ __forceinline__ void mma16816(float* c, uint32_t a0, uint32_t a1,
                                         uint32_t a2, uint32_t a3,
                                         uint32_t b0, uint32_t b1) {
    asm volatile("mma.sync.aligned.m16n8k16.row.col.f32.f16.f16.f32 "
                 "{%0,%1,%2,%3}, {%4,%5,%6,%7}, {%8,%9}, {%0,%1,%2,%3};"
                 : "+f"(c[0]), "+f"(c[1]), "+f"(c[2]), "+f"(c[3])
                 : "r"(a0), "r"(a1), "r"(a2), "r"(a3), "r"(b0), "r"(b1));
}

// streaming (evict-first) 16B accesses via .cs qualifier
__device__ __forceinline__ uint4 ldg_cs(const uint4* p) { return __ldcs(p); }
__device__ __forceinline__ void  stg_cs(uint4* p, uint4 v) { __stcs(p, v); }

// ---------------- init / CSR ----------------
__global__ void k_zero() {
    int i = blockIdx.x * blockDim.x + threadIdx.x;
    if (i <= NN)     g_off[i] = 0;
    if (i <  NN)     g_cursor[i] = 0;
    if (i <  NG * H) g_pool[i] = 0.f;
    if (i <  NG)     g_cnt[i] = 0.f;
}

__global__ void k_embed(const int* __restrict__ x, const float* __restrict__ emb) {
    int idx = blockIdx.x * blockDim.x + threadIdx.x;
    if (idx >= NN * H) return;
    int i = idx >> 7, c = idx & (H - 1);
    float v = emb[x[i] * H + c];
    g_h[idx] = v;
    __half hi = __float2half(v);
    g_hh_hi[idx] = hi;
    g_hh_lo[idx] = __float2half(v - __half2float(hi));
}

// eattr fp32 -> split fp16 rows (32 hi | 32 lo), done once
__global__ void k_econv(const float* __restrict__ eattr) {
    int idx = blockIdx.x * blockDim.x + threadIdx.x;
    if (idx >= NE * 4) return;
    int r = idx >> 2, c8 = (idx & 3) * 8;
    const float* s = eattr + (size_t)r * 32 + c8;
    float4 f0 = *(const float4*)s;
    float4 f1 = *(const float4*)(s + 4);
    float fv[8] = {f0.x, f0.y, f0.z, f0.w, f1.x, f1.y, f1.z, f1.w};
    __half hv[8], lv[8];
    #pragma unroll
    for (int j = 0; j < 8; j++) {
        hv[j] = __float2half(fv[j]);
        lv[j] = __float2half(fv[j] - __half2float(hv[j]));
    }
    *(uint4*)(g_ea + (size_t)r * 64 + c8)      = *(uint4*)hv;
    *(uint4*)(g_ea + (size_t)r * 64 + 32 + c8) = *(uint4*)lv;
}

__global__ void k_count(const int* __restrict__ ei) {
    int e = blockIdx.x * blockDim.x + threadIdx.x;
    if (e < NE) atomicAdd(&g_off[ei[NE + e] + 1], 1);
}

__global__ void k_scan1() {
    __shared__ int s[1024];
    int i = blockIdx.x * 1024 + threadIdx.x;
    int v = (i <= NN) ? g_off[i] : 0;
    s[threadIdx.x] = v;
    __syncthreads();
    #pragma unroll
    for (int d = 1; d < 1024; d <<= 1) {
        int t = (threadIdx.x >= d) ? s[threadIdx.x - d] : 0;
        __syncthreads();
        s[threadIdx.x] += t;
        __syncthreads();
    }
    if (i <= NN) g_off[i] = s[threadIdx.x];
    if (threadIdx.x == 1023) g_bsum[blockIdx.x] = s[1023];
}

__global__ void k_scan2() {
    if (threadIdx.x == 0) {
        int run = 0;
        for (int b = 0; b < NBLK; b++) { g_bpre[b] = run; run += g_bsum[b]; }
    }
}

__global__ void k_scan3() {
    int i = blockIdx.x * 1024 + threadIdx.x;
    if (blockIdx.x > 0 && i <= NN) g_off[i] += g_bpre[blockIdx.x];
}

__global__ void k_scatter(const int* __restrict__ ei) {
    int e = blockIdx.x * blockDim.x + threadIdx.x;
    if (e >= NE) return;
    int s = ei[e], d = ei[NE + e];
    int p = g_off[d] + atomicAdd(&g_cursor[d], 1);
    g_src[p] = s;
    g_eid[p] = e;
}

// ---------------- weight pack: fragment-major, split fp16 ----------------
// node out col n: [0,128)=B<-Wf[128+k][n], [128,256)=D<-Ws[128+k][n-128],
//                 [256,384)=A<-Wf[k][n-256], [384,512)=C<-Ws[k][n-384]
// edge out col n: [0,128)=cf<-Wf[256+k][n], [128,256)=cs<-Ws[256+k][n-128]
__device__ __forceinline__ float nodeW(const float* Wf, const float* Ws, int n, int k) {
    if (n < 128)      return Wf[(128 + k) * H + n];
    else if (n < 256) return Ws[(128 + k) * H + (n - 128)];
    else if (n < 384) return Wf[k * H + (n - 256)];
    else              return Ws[k * H + (n - 384)];
}

__global__ void k_pack(const float* __restrict__ Wf, const float* __restrict__ bf,
                       const float* __restrict__ Ws, const float* __restrict__ bs) {
    int idx = blockIdx.x * blockDim.x + threadIdx.x;
    if (idx < 65536) {                       // node frags: t(64) ks(8) lane(32) w(4)
        int w = idx & 3, lane = (idx >> 2) & 31, ks = (idx >> 7) & 7, t = idx >> 10;
        int r = w & 1, hilo = w >> 1;
        int n = t * 8 + (lane >> 2);
        int k0 = ks * 16 + (lane & 3) * 2 + r * 8;
        float v0 = nodeW(Wf, Ws, n, k0);
        float v1 = nodeW(Wf, Ws, n, k0 + 1);
        __half h0 = __float2half(v0), h1 = __float2half(v1);
        __half2 out;
        if (hilo == 0) out = __halves2half2(h0, h1);
        else out = __halves2half2(__float2half(v0 - __half2float(h0)),
                                  __float2half(v1 - __half2float(h1)));
        ((uint32_t*)g_wnp)[idx] = *(uint32_t*)&out;
    } else if (idx < 65536 + 8192) {         // edge frags: t(32) ks(2) lane(32) w(4)
        int i2 = idx - 65536;
        int w = i2 & 3, lane = (i2 >> 2) & 31, ks = (i2 >> 7) & 1, t = i2 >> 8;
        int r = w & 1, hilo = w >> 1;
        int n = t * 8 + (lane >> 2);
        int k0 = ks * 16 + (lane & 3) * 2 + r * 8;
        float v0, v1;
        if (n < 128) { v0 = Wf[(256 + k0) * H + n]; v1 = Wf[(256 + k0 + 1) * H + n]; }
        else         { v0 = Ws[(256 + k0) * H + n - 128]; v1 = Ws[(256 + k0 + 1) * H + n - 128]; }
        __half h0 = __float2half(v0), h1 = __float2half(v1);
        __half2 out;
        if (hilo == 0) out = __halves2half2(h0, h1);
        else out = __halves2half2(__float2half(v0 - __half2float(h0)),
                                  __float2half(v1 - __half2float(h1)));
        ((uint32_t*)g_wep)[i2] = *(uint32_t*)&out;
    } else if (idx < 65536 + 8192 + 256) {
        int c = idx - (65536 + 8192);
        if (c < 128) g_bA[c] = bf[c];
        else         g_bC[c - 128] = bs[c - 128];
    }
}

// ---------------- node GEMM (split-fp16 3-pass HMMA, frag-packed B) ----------------
__global__ __launch_bounds__(256) void gemm_node() {
    extern __shared__ __half sm[];
    __half* sH = sm;                 // 128 x 136
    __half* sL = sm + 128 * 136;
    int tid = threadIdx.x;
    int m0 = blockIdx.x * 128;

    for (int i = tid; i < 4096; i += 256) {
        int half_sel = i >> 11;
        int r = (i >> 4) & 127, c = i & 15;
        uint4 v = make_uint4(0, 0, 0, 0);
        if (m0 + r < NN) {
            const __half* src = half_sel ? g_hh_lo : g_hh_hi;
            v = *(const uint4*)(src + (size_t)(m0 + r) * 128 + c * 8);
        }
        __half* dstp = half_sel ? sL : sH;
        *(uint4*)(dstp + r * 136 + c * 8) = v;
    }
    __syncthreads();

    int w = tid >> 5, lane = tid & 31;
    int g = lane >> 2, tig = lane & 3;
    int row_l = w * 16 + g;
    int grow0 = m0 + row_l, grow1 = grow0 + 8;

    for (int q = 0; q < 8; q++) {
        float acc[8][4];
        #pragma unroll
        for (int i = 0; i < 8; i++)
            #pragma unroll
            for (int j = 0; j < 4; j++) acc[i][j] = 0.f;

        #pragma unroll
        for (int ks = 0; ks < 8; ks++) {
            const __half* apH = sH + row_l * 136 + ks * 16 + tig * 2;
            const __half* apL = sL + row_l * 136 + ks * 16 + tig * 2;
            uint32_t aH0 = *(const uint32_t*)apH;
            uint32_t aH1 = *(const uint32_t*)(apH + 8 * 136);
            uint32_t aH2 = *(const uint32_t*)(apH + 8);
            uint32_t aH3 = *(const uint32_t*)(apH + 8 * 136 + 8);
            uint32_t aL0 = *(const uint32_t*)apL;
            uint32_t aL1 = *(const uint32_t*)(apL + 8 * 136);
            uint32_t aL2 = *(const uint32_t*)(apL + 8);
            uint32_t aL3 = *(const uint32_t*)(apL + 8 * 136 + 8);
            #pragma unroll
            for (int i = 0; i < 8; i++) {
                int t = (q < 4) ? ((i < 4) ? (q * 4 + i) : (16 + q * 4 + i - 4))
                                : (32 + (q - 4) * 8 + i);
                uint4 f = g_wnp[(t * 8 + ks) * 32 + lane];   // b0hi,b1hi,b0lo,b1lo
                mma16816(acc[i], aH0, aH1, aH2, aH3, f.x, f.y);
                mma16816(acc[i], aH0, aH1, aH2, aH3, f.z, f.w);
                mma16816(acc[i], aL0, aL1, aL2, aL3, f.x, f.y);
            }
        }

        if (q < 4) {       // B|D fp32 interleaved
            #pragma unroll
            for (int i = 0; i < 4; i++) {
                int col = q * 32 + i * 8 + tig * 2;
                if (grow0 < NN) {
                    float4 o = make_float4(acc[i][0], acc[i + 4][0], acc[i][1], acc[i + 4][1]);
                    *(float4*)(g_bdf + (size_t)grow0 * 256 + col * 2) = o;
                }
                if (grow1 < NN) {
                    float4 o = make_float4(acc[i][2], acc[i + 4][2], acc[i][3], acc[i + 4][3]);
                    *(float4*)(g_bdf + (size_t)grow1 * 256 + col * 2) = o;
                }
            }
        } else {           // A|C plain fp32
            #pragma unroll
            for (int i = 0; i < 8; i++) {
                int col = (q - 4) * 64 + i * 8 + tig * 2;
                if (grow0 < NN)
                    *(float2*)(g_ac + (size_t)grow0 * 256 + col) = make_float2(acc[i][0], acc[i][1]);
                if (grow1 < NN)
                    *(float2*)(g_ac + (size_t)grow1 * 256 + col) = make_float2(acc[i][2], acc[i][3]);
            }
        }
    }
}

// ---------------- edge GEMM (split-fp16 3-pass HMMA, staged coalesced output) -------
#define SROW 528
__global__ __launch_bounds__(256) void gemm_edge() {
    __shared__ __half sH[64 * 40];
    __shared__ __half sL[64 * 40];
    __shared__ char  stage[64 * SROW];     // 64 edges x 512B (+16B pad)
    int tid = threadIdx.x;
    int m0 = blockIdx.x * 64;

    for (int i = tid; i < 512; i += 256) {       // 64 rows x 8 uint4 (128B rows)
        int r = i >> 3, seg = i & 7;
        uint4 v = ldg_cs((const uint4*)(g_ea + (size_t)(m0 + r) * 64 + seg * 8));
        if (seg < 4) *(uint4*)(sH + r * 40 + seg * 8) = v;
        else         *(uint4*)(sL + r * 40 + (seg - 4) * 8) = v;
    }
    __syncthreads();

    int w = tid >> 5, lane = tid & 31;
    int mg = w >> 1, nh = w & 1;
    int g = lane >> 2, tig = lane & 3;
    int row_l = mg * 16 + g;

    float af[8][4], as_[8][4];
    #pragma unroll
    for (int i = 0; i < 8; i++)
        #pragma unroll
        for (int j = 0; j < 4; j++) { af[i][j] = 0.f; as_[i][j] = 0.f; }

    #pragma unroll
    for (int ks = 0; ks < 2; ks++) {
        const __half* apH = sH + row_l * 40 + ks * 16 + tig * 2;
        const __half* apL = sL + row_l * 40 + ks * 16 + tig * 2;
        uint32_t aH0 = *(const uint32_t*)apH;
        uint32_t aH1 = *(const uint32_t*)(apH + 8 * 40);
        uint32_t aH2 = *(const uint32_t*)(apH + 8);
        uint32_t aH3 = *(const uint32_t*)(apH + 8 * 40 + 8);
        uint32_t aL0 = *(const uint32_t*)apL;
        uint32_t aL1 = *(const uint32_t*)(apL + 8 * 40);
        uint32_t aL2 = *(const uint32_t*)(apL + 8);
        uint32_t aL3 = *(const uint32_t*)(apL + 8 * 40 + 8);
        #pragma unroll
        for (int p = 0; p < 8; p++) {
            int tf = nh * 8 + p;
            uint4 ff = g_wep[(tf * 2 + ks) * 32 + lane];
            uint4 fs = g_wep[((tf + 16) * 2 + ks) * 32 + lane];
            mma16816(af[p],  aH0, aH1, aH2, aH3, ff.x, ff.y);
            mma16816(af[p],  aH0, aH1, aH2, aH3, ff.z, ff.w);
            mma16816(af[p],  aL0, aL1, aL2, aL3, ff.x, ff.y);
            mma16816(as_[p], aH0, aH1, aH2, aH3, fs.x, fs.y);
            mma16816(as_[p], aH0, aH1, aH2, aH3, fs.z, fs.w);
            mma16816(as_[p], aL0, aL1, aL2, aL3, fs.x, fs.y);
        }
    }

    // stage: interleave (cf,cs) -> half2 pairs into 512B rows
    #pragma unroll
    for (int p = 0; p < 8; p++) {
        int cb = nh * 256 + p * 32 + tig * 8;    // byte offset within row
        __half2 o[2];
        o[0] = __floats2half2_rn(af[p][0], as_[p][0]);
        o[1] = __floats2half2_rn(af[p][1], as_[p][1]);
        *(uint2*)(stage + row_l * SROW + cb) = *(uint2*)o;
        o[0] = __floats2half2_rn(af[p][2], as_[p][2]);
        o[1] = __floats2half2_rn(af[p][3], as_[p][3]);
        *(uint2*)(stage + (row_l + 8) * SROW + cb) = *(uint2*)o;
    }
    __syncthreads();

    // coalesced streaming writeout: 64 rows x 512B
    for (int i = tid; i < 2048; i += 256) {
        int row = i >> 5, seg = i & 31;
        uint4 v = *(const uint4*)(stage + row * SROW + seg * 16);
        stg_cs((uint4*)((char*)g_cc + (size_t)(m0 + row) * 512 + seg * 16), v);
    }
}

// ---------------- edge aggregation: one warp per dst node ----------------
__device__ __forceinline__ float gatef(float gf, float gs) {
    float sig = __fdividef(1.f, 1.f + __expf(-gf));
    float sp  = fmaxf(gs, 0.f) + __logf(1.f + __expf(-fabsf(gs)));
    return sig * sp;
}

__global__ __launch_bounds__(256) void k_edge() {
    int w = (blockIdx.x * blockDim.x + threadIdx.x) >> 5;
    int lane = threadIdx.x & 31;
    if (w >= NN) return;
    int c4 = lane * 4;
    float4 acc = *(const float4*)&g_h[w * H + c4];
    float4 Av = *(const float4*)&g_ac[w * 256 + c4];
    float4 Cv = *(const float4*)&g_ac[w * 256 + 128 + c4];
    float4 bAv = *(const float4*)&g_bA[c4];
    float4 bCv = *(const float4*)&g_bC[c4];
    Av.x += bAv.x; Av.y += bAv.y; Av.z += bAv.z; Av.w += bAv.w;
    Cv.x += bCv.x; Cv.y += bCv.y; Cv.z += bCv.z; Cv.w += bCv.w;
    int e0 = g_off[w], e1 = g_off[w + 1];
    for (int e = e0; e < e1; e++) {
        int src = g_src[e];
        int eid = g_eid[e];
        float4 bd0 = *(const float4*)(g_bdf + (size_t)src * 256 + c4 * 2);      // B0,D0,B1,D1
        float4 bd1 = *(const float4*)(g_bdf + (size_t)src * 256 + c4 * 2 + 4);  // B2,D2,B3,D3
        uint4 ccv = ldg_cs((const uint4*)(g_cc + (size_t)eid * 128 + c4));      // streaming
        const __half2* ch = (const __half2*)&ccv;
        float2 c0 = __half22float2(ch[0]), c1 = __half22float2(ch[1]);
        float2 c2 = __half22float2(ch[2]), c3 = __half22float2(ch[3]);
        acc.x += gatef(Av.x + bd0.x + c0.x, Cv.x + bd0.y + c0.y);
        acc.y += gatef(Av.y + bd0.z + c1.x, Cv.y + bd0.w + c1.y);
        acc.z += gatef(Av.z + bd1.x + c2.x, Cv.z + bd1.y + c2.y);
        acc.w += gatef(Av.w + bd1.z + c3.x, Cv.w + bd1.w + c3.y);
    }
    acc.x = fmaxf(acc.x, 0.f);
    acc.y = fmaxf(acc.y, 0.f);
    acc.z = fmaxf(acc.z, 0.f);
    acc.w = fmaxf(acc.w, 0.f);
    *(float4*)&g_h[w * H + c4] = acc;
    __half hi[4], lo[4];
    hi[0] = __float2half(acc.x); lo[0] = __float2half(acc.x - __half2float(hi[0]));
    hi[1] = __float2half(acc.y); lo[1] = __float2half(acc.y - __half2float(hi[1]));
    hi[2] = __float2half(acc.z); lo[2] = __float2half(acc.z - __half2float(hi[2]));
    hi[3] = __float2half(acc.w); lo[3] = __float2half(acc.w - __half2float(hi[3]));
    *(uint2*)(g_hh_hi + w * H + c4) = *(uint2*)hi;
    *(uint2*)(g_hh_lo + w * H + c4) = *(uint2*)lo;
}

// ---------------- pooling + final linear ----------------
__global__ void k_pool(const int* __restrict__ batch) {
    int idx = blockIdx.x * blockDim.x + threadIdx.x;
    if (idx >= NN * H) return;
    int i = idx >> 7, c = idx & (H - 1);
    atomicAdd(&g_pool[batch[i] * H + c], g_h[idx]);
}

__global__ void k_cnt(const int* __restrict__ batch) {
    int i = blockIdx.x * blockDim.x + threadIdx.x;
    if (i < NN) atomicAdd(&g_cnt[batch[i]], 1.f);
}

__global__ void k_final(const float* __restrict__ Wlin, const float* __restrict__ blin,
                        float* __restrict__ out) {
    __shared__ float p[H];
    int g = blockIdx.x, j = threadIdx.x;
    float cnt = fmaxf(g_cnt[g], 1.f);
    p[j] = g_pool[g * H + j] / cnt;
    __syncthreads();
    float s = blin[j];
    #pragma unroll 8
    for (int k = 0; k < H; k++) s = fmaf(p[k], Wlin[k * H + j], s);
    out[g * H + j] = s;
}

// ---------------- launch ----------------
extern "C" void kernel_launch(void* const* d_in, const int* in_sizes, int n_in,
                              void* d_out, int out_size) {
    const int*   x     = (const int*)d_in[0];
    const int*   ei    = (const int*)d_in[1];
    const float* eattr = (const float*)d_in[2];
    const int*   batch = (const int*)d_in[3];
    const float* emb   = (const float*)d_in[4];
    const float* Wf[3] = {(const float*)d_in[5],  (const float*)d_in[9],  (const float*)d_in[13]};
    const float* bf[3] = {(const float*)d_in[6],  (const float*)d_in[10], (const float*)d_in[14]};
    const float* Ws[3] = {(const float*)d_in[7],  (const float*)d_in[11], (const float*)d_in[15]};
    const float* bs[3] = {(const float*)d_in[8],  (const float*)d_in[12], (const float*)d_in[16]};
    const float* Wlin  = (const float*)d_in[17];
    const float* blin  = (const float*)d_in[18];
    float* out = (float*)d_out;

    static int smem_set = 0;
    if (!smem_set) {
        cudaFuncSetAttribute(gemm_node, cudaFuncAttributeMaxDynamicSharedMemorySize,
                             2 * 128 * 136 * (int)sizeof(__half));
        smem_set = 1;
    }

    // launch order puts layer-0 gemm_edge at launch index 3 (the slot ncu captures)
    k_pack<<<(65536 + 8192 + 256 + 255) / 256, 256>>>(Wf[0], bf[0], Ws[0], bs[0]);   // 0
    k_econv<<<(NE * 4 + 255) / 256, 256>>>(eattr);                                    // 1
    k_embed<<<(NN * H + 255) / 256, 256>>>(x, emb);                                   // 2
    gemm_edge<<<NE / 64, 256>>>();                                                    // 3 <- ncu
    k_zero<<<(NG * H + 255) / 256, 256>>>();                                          // 4
    k_count<<<(NE + 255) / 256, 256>>>(ei);
    k_scan1<<<NBLK, 1024>>>();
    k_scan2<<<1, 32>>>();
    k_scan3<<<NBLK, 1024>>>();
    k_scatter<<<(NE + 255) / 256, 256>>>(ei);
    gemm_node<<<(NN + 127) / 128, 256, 2 * 128 * 136 * sizeof(__half)>>>();
    k_edge<<<(NN * 32 + 255) / 256, 256>>>();

    for (int l = 1; l < 3; l++) {
        k_pack<<<(65536 + 8192 + 256 + 255) / 256, 256>>>(Wf[l], bf[l], Ws[l], bs[l]);
        gemm_node<<<(NN + 127) / 128, 256, 2 * 128 * 136 * sizeof(__half)>>>();
        gemm_edge<<<NE / 64, 256>>>();
        k_edge<<<(NN * 32 + 255) / 256, 256>>>();
    }

    k_pool<<<(NN * H + 255) / 256, 256>>>(batch);
    k_cnt<<<(NN + 255) / 256, 256>>>(batch);
    k_final<<<NG, H>>>(Wlin, blin, out);
}